// round 9
// baseline (speedup 1.0000x reference)
#include <cuda_runtime.h>
#include <cuda_bf16.h>

#define EPSF 1e-10f
#define CHUNK 1024   // float4-vectors per work chunk (32 KB of data)

// Persistent scratch (no allocations allowed). Reset by the last block each
// run, so every graph replay starts from a clean state.
__device__ double g_acc = 0.0;
__device__ unsigned int g_done = 0;
__device__ unsigned int g_ticket = 0;

__device__ __forceinline__ float elem_term_acc(float p, int y, float neg_lam, float acc) {
    // y==0 -> -log(1 - p + eps); else -> -lam * log(p + eps)
    // One FADD (arg), one MUFU (log), one FFMA (scale+accumulate).
    bool neg = (y == 0);
    float arg = neg ? ((1.0f + EPSF) - p) : (p + EPSF);
    float m   = neg ? -1.0f : neg_lam;
    return fmaf(m, __logf(arg), acc);
}

__global__ void __launch_bounds__(256, 8)
sparse_loss_fused(const float* __restrict__ pred,
                  const int* __restrict__ y,
                  const int* __restrict__ lamda_raw,
                  float* __restrict__ out,
                  int n) {
    // Disambiguate lamda dtype: small non-negative int bit-pattern -> integer,
    // otherwise reinterpret bits as float. (int 5 and float 5.0f both -> 5.0f)
    int ibits = *lamda_raw;
    float lam = (ibits >= 0 && ibits < 1000000) ? (float)ibits : __int_as_float(ibits);
    float neg_lam = -lam;

    int nvec = n >> 2;  // float4 count
    int nchunks = (nvec + CHUNK - 1) / CHUNK;
    const float4* __restrict__ p4 = (const float4*)pred;
    const int4*   __restrict__ y4 = (const int4*)y;

    float a0 = 0.0f, a1 = 0.0f, a2 = 0.0f, a3 = 0.0f;

    // ── Dynamic work stealing: CTAs grab 32KB chunks off a global ticket.
    // The next ticket is prefetched (ping-pong shared slots) so the ATOMG
    // latency hides under the current chunk's DRAM traffic.
    __shared__ int s_tick[2];
    if (threadIdx.x == 0) s_tick[0] = (int)atomicAdd(&g_ticket, 1u);
    __syncthreads();
    int parity = 0;
    int cur = s_tick[0];

    while (cur < nchunks) {
        if (threadIdx.x == 0)
            s_tick[parity ^ 1] = (int)atomicAdd(&g_ticket, 1u);

        int base = cur * CHUNK + threadIdx.x;
        #pragma unroll
        for (int j = 0; j < 2; j++) {
            int i0 = base + j * 512;
            int i1 = i0 + 256;
            if (i1 < nvec) {            // common case: full batched pair
                float4 p0 = __ldcs(p4 + i0);
                float4 p1 = __ldcs(p4 + i1);
                int4   t0 = __ldcs(y4 + i0);
                int4   t1 = __ldcs(y4 + i1);
                a0 = elem_term_acc(p0.x, t0.x, neg_lam, a0);
                a1 = elem_term_acc(p0.y, t0.y, neg_lam, a1);
                a2 = elem_term_acc(p0.z, t0.z, neg_lam, a2);
                a3 = elem_term_acc(p0.w, t0.w, neg_lam, a3);
                a0 = elem_term_acc(p1.x, t1.x, neg_lam, a0);
                a1 = elem_term_acc(p1.y, t1.y, neg_lam, a1);
                a2 = elem_term_acc(p1.z, t1.z, neg_lam, a2);
                a3 = elem_term_acc(p1.w, t1.w, neg_lam, a3);
            } else if (i0 < nvec) {     // ragged last chunk
                float4 p = __ldcs(p4 + i0);
                int4   t = __ldcs(y4 + i0);
                a0 = elem_term_acc(p.x, t.x, neg_lam, a0);
                a1 = elem_term_acc(p.y, t.y, neg_lam, a1);
                a2 = elem_term_acc(p.z, t.z, neg_lam, a2);
                a3 = elem_term_acc(p.w, t.w, neg_lam, a3);
            }
        }
        // scalar tail (n not divisible by 4): owner of chunk 0 handles it
        if (cur == 0) {
            for (int j = (nvec << 2) + (int)threadIdx.x; j < n; j += 256)
                a0 = elem_term_acc(pred[j], y[j], neg_lam, a0);
        }

        __syncthreads();            // s_tick[parity^1] now valid for all
        parity ^= 1;
        cur = s_tick[parity];
    }

    float acc = (a0 + a1) + (a2 + a3);

    // warp reduce
    #pragma unroll
    for (int off = 16; off > 0; off >>= 1)
        acc += __shfl_down_sync(0xFFFFFFFFu, acc, off);

    __shared__ float wsum[8];
    int lane = threadIdx.x & 31;
    int warp = threadIdx.x >> 5;
    if (lane == 0) wsum[warp] = acc;
    __syncthreads();

    __shared__ bool s_last;
    if (warp == 0) {
        float b = (lane < (blockDim.x >> 5)) ? wsum[lane] : 0.0f;
        #pragma unroll
        for (int off = 4; off > 0; off >>= 1)
            b += __shfl_down_sync(0xFFFFFFFFu, b, off);
        if (lane == 0) {
            atomicAdd(&g_acc, (double)b);
            __threadfence();
            unsigned prev = atomicAdd(&g_done, 1u);
            s_last = (prev == gridDim.x - 1);
        }
    }
    __syncthreads();

    // Last block to finish: publish result and reset ALL state for next replay.
    if (s_last && threadIdx.x == 0) {
        double total = atomicAdd(&g_acc, 0.0);  // fenced read
        out[0] = (float)(total / (double)n);
        g_acc = 0.0;
        g_ticket = 0;
        __threadfence();
        g_done = 0;
    }
}

extern "C" void kernel_launch(void* const* d_in, const int* in_sizes, int n_in,
                              void* d_out, int out_size) {
    const float* pred  = (const float*)d_in[0];
    const int*   y     = (const int*)d_in[1];
    const int*   lamda = (const int*)d_in[2];
    int n = in_sizes[0];

    const int threads = 256;
    int blocks = 148 * 8;  // one full persistent wave at 8 CTAs/SM
    int nvec = (n >> 2) > 0 ? (n >> 2) : 1;
    int nchunks = (nvec + CHUNK - 1) / CHUNK;
    if (blocks > nchunks) blocks = nchunks;
    if (blocks < 1) blocks = 1;

    sparse_loss_fused<<<blocks, threads>>>(pred, y, lamda, (float*)d_out, n);
}